// round 8
// baseline (speedup 1.0000x reference)
#include <cuda_runtime.h>
#include <cstdint>

#define B_    64
#define T_    2048
#define DIN   256
#define DH    256
#define DC    256
#define DOUT  256
#define G3    768   // 3 gates * 256

// Scratch (allocation-free rule: __device__ globals)
__device__ float g_Gx[(size_t)B_ * T_ * G3];  // x-part gate preactivations (+bias)
__device__ float g_H [(size_t)B_ * T_ * DH];  // h_t for all t (for output GEMM)

// ---------------- helpers ----------------

__device__ __forceinline__ float2 ffma2(float2 a, float2 b, float2 c) {
    union U { float2 f; unsigned long long u; };
    U ua, ub, uc, ud;
    ua.f = a; ub.f = b; uc.f = c;
    asm("fma.rn.f32x2 %0, %1, %2, %3;"
        : "=l"(ud.u) : "l"(ua.u), "l"(ub.u), "l"(uc.u));
    return ud.f;
}

__device__ __forceinline__ uint32_t smem_u32(const void* p) {
    uint32_t a;
    asm("{ .reg .u64 t; cvta.to.shared.u64 t, %1; cvt.u32.u64 %0, t; }"
        : "=r"(a) : "l"(p));
    return a;
}

__device__ __forceinline__ void cluster_sync_() {
    asm volatile("barrier.cluster.arrive.aligned;" ::: "memory");
    asm volatile("barrier.cluster.wait.aligned;" ::: "memory");
}

__device__ __forceinline__ void mbar_init1(uint32_t mbar) {
    asm volatile("mbarrier.init.shared.b64 [%0], %1;" :: "r"(mbar), "r"(1u) : "memory");
}

__device__ __forceinline__ void mbar_expect(uint32_t mbar, uint32_t bytes) {
    asm volatile("mbarrier.arrive.expect_tx.shared.b64 _, [%0], %1;"
                 :: "r"(mbar), "r"(bytes) : "memory");
}

__device__ __forceinline__ void mbar_wait(uint32_t mbar, uint32_t parity) {
    asm volatile(
        "{\n\t"
        ".reg .pred P;\n"
        "W%=:\n\t"
        "mbarrier.try_wait.parity.acquire.cta.shared::cta.b64 P, [%0], %1, 0x989680;\n\t"
        "@P bra.uni D%=;\n\t"
        "bra.uni W%=;\n"
        "D%=:\n\t"
        "}"
        :: "r"(mbar), "r"(parity) : "memory");
}

// Bulk DSMEM copy: local smem region -> same offset in peer rank's smem,
// completion tx-counted on the peer's mbarrier.
__device__ __forceinline__ void bulk_to_rank(uint32_t dst_l, uint32_t src_l,
                                             uint32_t mbar_l, uint32_t rank,
                                             uint32_t bytes) {
    asm volatile(
        "{\n\t"
        ".reg .b32 rd, rm;\n\t"
        "mapa.shared::cluster.u32 rd, %0, %2;\n\t"
        "mapa.shared::cluster.u32 rm, %1, %2;\n\t"
        "cp.async.bulk.shared::cluster.shared::cta.mbarrier::complete_tx::bytes "
        "[rd], [%3], %4, [rm];\n\t"
        "}"
        :: "r"(dst_l), "r"(mbar_l), "r"(rank), "r"(src_l), "r"(bytes) : "memory");
}

__device__ __forceinline__ void fence_proxy_async_() {
    asm volatile("fence.proxy.async.shared::cta;" ::: "memory");
}

__device__ __forceinline__ float sigmoidf_(float x) {
    return __fdividef(1.0f, 1.0f + __expf(-x));
}

__device__ __forceinline__ float tanhf_(float x) {
    return 1.0f - __fdividef(2.0f, 1.0f + __expf(2.0f * x));
}

// ================= GEMM core: 128x128 tile, BK=16, double-buffered =================

__global__ __launch_bounds__(256) void gemm_gx(
    const float* __restrict__ X,
    const float* __restrict__ Wf, const float* __restrict__ Wi, const float* __restrict__ Wo,
    const float* __restrict__ bf, const float* __restrict__ bi, const float* __restrict__ bo,
    const int* __restrict__ Np)
{
    const int N = *Np;
    const int m0 = blockIdx.y * 128;
    if (m0 >= B_ * N) return;
    const int j0v = blockIdx.x * 128;
    const int g  = j0v >> 8;
    const int d0 = j0v & 255;
    const float* Wg = (g == 0) ? Wf : ((g == 1) ? Wi : Wo);
    const float* bg = (g == 0) ? bf : ((g == 1) ? bi : bo);

    __shared__ float2 As2[2][8][128];
    __shared__ float2 Bs2[2][8][128];

    const int tid = threadIdx.x;
    const int tx = tid & 15, ty = tid >> 4;

    const int ra = tid >> 1, ha = tid & 1;
    int mg = m0 + ra; if (mg >= B_ * N) mg = B_ * N - 1;
    const int bb = mg / N, tt = mg % N;
    const float* arow = X + (size_t)(bb * T_ + tt) * DIN + 8 * ha;

    const int kp0 = tid >> 5;
    const int np0 = tid & 31;
    const float* bcol = Wg + d0 + 2 * np0;

    float4 a0, a1;
    float2 v00, v01, v10, v11;

    a0 = *reinterpret_cast<const float4*>(arow);
    a1 = *reinterpret_cast<const float4*>(arow + 4);
    v00 = *reinterpret_cast<const float2*>(bcol + (size_t)(2 * kp0) * DC);
    v01 = *reinterpret_cast<const float2*>(bcol + (size_t)(2 * kp0 + 1) * DC);
    v10 = *reinterpret_cast<const float2*>(bcol + (size_t)(2 * kp0) * DC + 64);
    v11 = *reinterpret_cast<const float2*>(bcol + (size_t)(2 * kp0 + 1) * DC + 64);

    As2[0][4 * ha + 0][ra] = make_float2(a0.x, a0.y);
    As2[0][4 * ha + 1][ra] = make_float2(a0.z, a0.w);
    As2[0][4 * ha + 2][ra] = make_float2(a1.x, a1.y);
    As2[0][4 * ha + 3][ra] = make_float2(a1.z, a1.w);
    *reinterpret_cast<float4*>(&Bs2[0][kp0][2 * np0]) =
        make_float4(v00.x, v01.x, v00.y, v01.y);
    *reinterpret_cast<float4*>(&Bs2[0][kp0][2 * np0 + 64]) =
        make_float4(v10.x, v11.x, v10.y, v11.y);
    __syncthreads();

    float2 acc[8][8];
    #pragma unroll
    for (int i = 0; i < 8; i++)
        #pragma unroll
        for (int j = 0; j < 8; j++) acc[i][j] = make_float2(0.f, 0.f);

    #pragma unroll 1
    for (int c = 0; c < 16; ++c) {
        const int buf = c & 1;
        if (c + 1 < 16) {
            const int kk = (c + 1) * 16;
            a0 = *reinterpret_cast<const float4*>(arow + kk);
            a1 = *reinterpret_cast<const float4*>(arow + kk + 4);
            v00 = *reinterpret_cast<const float2*>(bcol + (size_t)(kk + 2 * kp0) * DC);
            v01 = *reinterpret_cast<const float2*>(bcol + (size_t)(kk + 2 * kp0 + 1) * DC);
            v10 = *reinterpret_cast<const float2*>(bcol + (size_t)(kk + 2 * kp0) * DC + 64);
            v11 = *reinterpret_cast<const float2*>(bcol + (size_t)(kk + 2 * kp0 + 1) * DC + 64);
        }
        #pragma unroll
        for (int kp = 0; kp < 8; kp++) {
            float2 a2[8], b2[8];
            #pragma unroll
            for (int i = 0; i < 4; i++) {
                float4 t = *reinterpret_cast<const float4*>(&As2[buf][kp][32 * i + 2 * ty]);
                a2[2 * i]     = make_float2(t.x, t.y);
                a2[2 * i + 1] = make_float2(t.z, t.w);
            }
            #pragma unroll
            for (int j = 0; j < 4; j++) {
                float4 t = *reinterpret_cast<const float4*>(&Bs2[buf][kp][32 * j + 2 * tx]);
                b2[2 * j]     = make_float2(t.x, t.y);
                b2[2 * j + 1] = make_float2(t.z, t.w);
            }
            #pragma unroll
            for (int i = 0; i < 8; i++)
                #pragma unroll
                for (int j = 0; j < 8; j++)
                    acc[i][j] = ffma2(a2[i], b2[j], acc[i][j]);
        }
        if (c + 1 < 16) {
            const int nb = buf ^ 1;
            As2[nb][4 * ha + 0][ra] = make_float2(a0.x, a0.y);
            As2[nb][4 * ha + 1][ra] = make_float2(a0.z, a0.w);
            As2[nb][4 * ha + 2][ra] = make_float2(a1.x, a1.y);
            As2[nb][4 * ha + 3][ra] = make_float2(a1.z, a1.w);
            *reinterpret_cast<float4*>(&Bs2[nb][kp0][2 * np0]) =
                make_float4(v00.x, v01.x, v00.y, v01.y);
            *reinterpret_cast<float4*>(&Bs2[nb][kp0][2 * np0 + 64]) =
                make_float4(v10.x, v11.x, v10.y, v11.y);
        }
        __syncthreads();
    }

    float bgv[8];
    #pragma unroll
    for (int u = 0; u < 4; u++) {
        bgv[2 * u]     = bg[d0 + 32 * u + 2 * tx];
        bgv[2 * u + 1] = bg[d0 + 32 * u + 2 * tx + 1];
    }
    #pragma unroll
    for (int i = 0; i < 8; i++) {
        const int m = m0 + 32 * (i >> 1) + 2 * ty + (i & 1);
        if (m < B_ * N) {
            float* crow = g_Gx + (size_t)m * G3 + j0v;
            #pragma unroll
            for (int u = 0; u < 4; u++)
                *reinterpret_cast<float2*>(crow + 32 * u + 2 * tx) =
                    make_float2(acc[i][2 * u].x + acc[i][2 * u].y + bgv[2 * u],
                                acc[i][2 * u + 1].x + acc[i][2 * u + 1].y + bgv[2 * u + 1]);
        }
    }
}

// ---------------- GEMM 3: outs = sigmoid(H @ Wout + bout) ----------------

__global__ __launch_bounds__(256) void gemm_out(
    const float* __restrict__ Wout, const float* __restrict__ bout,
    float* __restrict__ out, const int* __restrict__ Np)
{
    const int N = *Np;
    const int m0 = blockIdx.y * 128;
    if (m0 >= B_ * N) return;
    const int j0v = blockIdx.x * 128;

    __shared__ float2 As2[2][8][128];
    __shared__ float2 Bs2[2][8][128];

    const int tid = threadIdx.x;
    const int tx = tid & 15, ty = tid >> 4;

    const int ra = tid >> 1, ha = tid & 1;
    int mg = m0 + ra; if (mg >= B_ * N) mg = B_ * N - 1;
    const float* arow = g_H + (size_t)mg * DH + 8 * ha;

    const int kp0 = tid >> 5;
    const int np0 = tid & 31;
    const float* bcol = Wout + j0v + 2 * np0;

    float4 a0, a1;
    float2 v00, v01, v10, v11;

    a0 = *reinterpret_cast<const float4*>(arow);
    a1 = *reinterpret_cast<const float4*>(arow + 4);
    v00 = *reinterpret_cast<const float2*>(bcol + (size_t)(2 * kp0) * DOUT);
    v01 = *reinterpret_cast<const float2*>(bcol + (size_t)(2 * kp0 + 1) * DOUT);
    v10 = *reinterpret_cast<const float2*>(bcol + (size_t)(2 * kp0) * DOUT + 64);
    v11 = *reinterpret_cast<const float2*>(bcol + (size_t)(2 * kp0 + 1) * DOUT + 64);

    As2[0][4 * ha + 0][ra] = make_float2(a0.x, a0.y);
    As2[0][4 * ha + 1][ra] = make_float2(a0.z, a0.w);
    As2[0][4 * ha + 2][ra] = make_float2(a1.x, a1.y);
    As2[0][4 * ha + 3][ra] = make_float2(a1.z, a1.w);
    *reinterpret_cast<float4*>(&Bs2[0][kp0][2 * np0]) =
        make_float4(v00.x, v01.x, v00.y, v01.y);
    *reinterpret_cast<float4*>(&Bs2[0][kp0][2 * np0 + 64]) =
        make_float4(v10.x, v11.x, v10.y, v11.y);
    __syncthreads();

    float2 acc[8][8];
    #pragma unroll
    for (int i = 0; i < 8; i++)
        #pragma unroll
        for (int j = 0; j < 8; j++) acc[i][j] = make_float2(0.f, 0.f);

    #pragma unroll 1
    for (int c = 0; c < 16; ++c) {
        const int buf = c & 1;
        if (c + 1 < 16) {
            const int kk = (c + 1) * 16;
            a0 = *reinterpret_cast<const float4*>(arow + kk);
            a1 = *reinterpret_cast<const float4*>(arow + kk + 4);
            v00 = *reinterpret_cast<const float2*>(bcol + (size_t)(kk + 2 * kp0) * DOUT);
            v01 = *reinterpret_cast<const float2*>(bcol + (size_t)(kk + 2 * kp0 + 1) * DOUT);
            v10 = *reinterpret_cast<const float2*>(bcol + (size_t)(kk + 2 * kp0) * DOUT + 64);
            v11 = *reinterpret_cast<const float2*>(bcol + (size_t)(kk + 2 * kp0 + 1) * DOUT + 64);
        }
        #pragma unroll
        for (int kp = 0; kp < 8; kp++) {
            float2 a2[8], b2[8];
            #pragma unroll
            for (int i = 0; i < 4; i++) {
                float4 t = *reinterpret_cast<const float4*>(&As2[buf][kp][32 * i + 2 * ty]);
                a2[2 * i]     = make_float2(t.x, t.y);
                a2[2 * i + 1] = make_float2(t.z, t.w);
            }
            #pragma unroll
            for (int j = 0; j < 4; j++) {
                float4 t = *reinterpret_cast<const float4*>(&Bs2[buf][kp][32 * j + 2 * tx]);
                b2[2 * j]     = make_float2(t.x, t.y);
                b2[2 * j + 1] = make_float2(t.z, t.w);
            }
            #pragma unroll
            for (int i = 0; i < 8; i++)
                #pragma unroll
                for (int j = 0; j < 8; j++)
                    acc[i][j] = ffma2(a2[i], b2[j], acc[i][j]);
        }
        if (c + 1 < 16) {
            const int nb = buf ^ 1;
            As2[nb][4 * ha + 0][ra] = make_float2(a0.x, a0.y);
            As2[nb][4 * ha + 1][ra] = make_float2(a0.z, a0.w);
            As2[nb][4 * ha + 2][ra] = make_float2(a1.x, a1.y);
            As2[nb][4 * ha + 3][ra] = make_float2(a1.z, a1.w);
            *reinterpret_cast<float4*>(&Bs2[nb][kp0][2 * np0]) =
                make_float4(v00.x, v01.x, v00.y, v01.y);
            *reinterpret_cast<float4*>(&Bs2[nb][kp0][2 * np0 + 64]) =
                make_float4(v10.x, v11.x, v10.y, v11.y);
        }
        __syncthreads();
    }

    float bgv[8];
    #pragma unroll
    for (int u = 0; u < 4; u++) {
        bgv[2 * u]     = bout[j0v + 32 * u + 2 * tx];
        bgv[2 * u + 1] = bout[j0v + 32 * u + 2 * tx + 1];
    }
    #pragma unroll
    for (int i = 0; i < 8; i++) {
        const int m = m0 + 32 * (i >> 1) + 2 * ty + (i & 1);
        if (m < B_ * N) {
            float* crow = out + (size_t)m * DOUT + j0v;
            #pragma unroll
            for (int u = 0; u < 4; u++)
                *reinterpret_cast<float2*>(crow + 32 * u + 2 * tx) =
                    make_float2(
                        sigmoidf_(acc[i][2 * u].x + acc[i][2 * u].y + bgv[2 * u]),
                        sigmoidf_(acc[i][2 * u + 1].x + acc[i][2 * u + 1].y + bgv[2 * u + 1]));
        }
    }
}

// ---------------- Recurrence: persistent, batch-parallel, 4-CTA clusters ----------------
// 32 clusters x 4 CTAs, batches {2c, 2c+1}. Rank r owns cell dims [r*64, r*64+64) for
// all 3 gates, Wh register-resident.
// h exchange: h_s is RANK-MAJOR so each rank's per-step contribution is one contiguous
// 512B block; owners STS locally, then ONE thread bulk-copies 512B to each of the 3
// peer ranks via cp.async.bulk.shared::cluster (tx-counted on peer mbar, expect=1536B).
// No per-step cluster.sync; local visibility via end-of-loop __syncthreads.

__global__ __launch_bounds__(384, 1) __cluster_dims__(4, 1, 1)
void lstm_rec(
    const float* __restrict__ h0, const float* __restrict__ c0,
    const float* __restrict__ Wf, const float* __restrict__ Wi, const float* __restrict__ Wo,
    float* __restrict__ out, const int* __restrict__ Np)
{
    const int N   = *Np;
    const int r   = blockIdx.x & 3;
    const int cid = blockIdx.x >> 2;
    const int b0  = cid * 2;
    const int tid = threadIdx.x;

    __shared__ __align__(16) float h_s[2][4][2][64];  // [parity][rank][batch][dim64]
    __shared__ float pre_s[2][192];                   // [batch][g*64+dd]
    __shared__ __align__(8) unsigned long long mbar[2];

    const int j  = tid >> 1;             // 0..191 : local gate-col
    const int ks = tid & 1;              // k-half
    const int g  = j >> 6;
    const int dd = j & 63;
    const int gd = r * 64 + dd;
    const float* Wg = (g == 0) ? Wf : ((g == 1) ? Wi : Wo);
    const float* wp = Wg + (size_t)(256 + ks * 128) * DC + gd;

    float2 w[64];
    #pragma unroll
    for (int q = 0; q < 64; q++)
        w[q] = make_float2(wp[(size_t)(2 * q) * DC], wp[(size_t)(2 * q + 1) * DC]);

    const uint32_t mb0 = smem_u32(&mbar[0]);
    const uint32_t mb1 = smem_u32(&mbar[1]);
    if (tid == 0) {
        mbar_init1(mb0);
        mbar_init1(mb1);
        mbar_expect(mb0, 1536);   // first use: h for step 2
        mbar_expect(mb1, 1536);   // first use: h for step 1
    }

    // init h (parity 0), rank-major layout
    for (int i = tid; i < 512; i += 384) {
        const int b = (i >> 6) & 1, rk = i >> 7, d = i & 63;
        h_s[0][rk][b][d] = h0[(b0 + b) * DH + rk * 64 + d];
    }
    float c_st = 0.f, h_loc = 0.f;
    const int pb = (tid < 128) ? (tid >> 6) : 0;
    const int pd = (tid < 128) ? (tid & 63) : 0;
    if (tid < 128) c_st = c0[(b0 + pb) * DC + r * 64 + pd];
    __syncthreads();
    cluster_sync_();   // all mbarriers initialized before any DSMEM traffic

    const int gcol = g * 256 + gd;
    float gx0 = 0.f, gx1 = 0.f;
    if (ks == 0) {
        gx0 = g_Gx[((size_t)(b0 + 0) * N + 0) * G3 + gcol];
        gx1 = g_Gx[((size_t)(b0 + 1) * N + 0) * G3 + gcol];
    }

    float* out_hf = out + (size_t)B_ * N * DOUT;
    float* out_cf = out_hf + B_ * DH;

    int ph0 = 0, ph1 = 0;

    for (int t = 0; t < N; t++) {
        const int p = t & 1;

        if (t > 0) {
            const uint32_t mb = p ? mb1 : mb0;
            mbar_wait(mb, (uint32_t)(p ? ph1 : ph0));
            if (p) ph1 ^= 1; else ph0 ^= 1;
            if (tid == 0) mbar_expect(mb, 1536);   // re-arm for step t+2
        }

        const float gxc0 = gx0, gxc1 = gx1;
        const int tn = (t + 1 < N) ? (t + 1) : t;
        if (ks == 0) {
            gx0 = g_Gx[((size_t)(b0 + 0) * N + tn) * G3 + gcol];
            gx1 = g_Gx[((size_t)(b0 + 1) * N + tn) * G3 + gcol];
        }

        #pragma unroll
        for (int b = 0; b < 2; b++) {
            // k-range [ks*128, ks*128+128) = rank chunks {2ks, 2ks+1}
            const float4* hA = reinterpret_cast<const float4*>(&h_s[p][2 * ks][b][0]);
            const float4* hB = reinterpret_cast<const float4*>(&h_s[p][2 * ks + 1][b][0]);
            float2 accA = make_float2(0.f, 0.f);
            float2 accB = make_float2(0.f, 0.f);
            #pragma unroll
            for (int q = 0; q < 16; q++) {
                float4 hv = hA[q];
                accA = ffma2(w[2 * q],     make_float2(hv.x, hv.y), accA);
                accB = ffma2(w[2 * q + 1], make_float2(hv.z, hv.w), accB);
            }
            #pragma unroll
            for (int q = 0; q < 16; q++) {
                float4 hv = hB[q];
                accA = ffma2(w[32 + 2 * q],     make_float2(hv.x, hv.y), accA);
                accB = ffma2(w[32 + 2 * q + 1], make_float2(hv.z, hv.w), accB);
            }
            float s = accA.x + accA.y + accB.x + accB.y;
            s += __shfl_xor_sync(0xffffffffu, s, 1);
            if (ks == 0) pre_s[b][j] = s + ((b == 0) ? gxc0 : gxc1);
        }
        __syncthreads();

        if (tid < 128) {
            const float pf = pre_s[pb][pd];
            const float pi = pre_s[pb][64 + pd];
            const float po = pre_s[pb][128 + pd];
            const float f  = sigmoidf_(pf);
            const float ig = sigmoidf_(pi);
            const float z  = tanhf_(pi);
            const float o  = sigmoidf_(po);
            c_st  = c_st * f + z * ig;
            h_loc = tanhf_(c_st) * o;

            if (t + 1 < N) {
                // local write of own chunk (covered by end-of-loop __syncthreads)
                h_s[1 - p][r][pb][pd] = h_loc;
            }
            g_H[((size_t)(b0 + pb) * N + t) * DH + r * 64 + pd] = h_loc;

            if (t + 1 < N) {
                asm volatile("bar.sync 1, 128;" ::: "memory");  // owner warps only
                if (tid == 0) {
                    fence_proxy_async_();
                    const uint32_t src = smem_u32(&h_s[1 - p][r][0][0]);
                    const uint32_t mbl = p ? mb0 : mb1;
                    const uint32_t r1 = (r + 1) & 3, r2 = (r + 2) & 3, r3 = (r + 3) & 3;
                    bulk_to_rank(src, src, mbl, r1, 512u);
                    bulk_to_rank(src, src, mbl, r2, 512u);
                    bulk_to_rank(src, src, mbl, r3, 512u);
                }
            }
        }
        __syncthreads();   // local h chunk visible to all warps for step t+1
    }

    if (tid < 128) {
        out_hf[(b0 + pb) * DH + r * 64 + pd] = h_loc;
        out_cf[(b0 + pb) * DC + r * 64 + pd] = c_st;
    }
    cluster_sync_();   // no CTA exits while peers could still be mid-step
}

// ---------------- launch ----------------

extern "C" void kernel_launch(void* const* d_in, const int* in_sizes, int n_in,
                              void* d_out, int out_size) {
    const float* x    = (const float*)d_in[0];
    const float* h0   = (const float*)d_in[1];
    const float* c0   = (const float*)d_in[2];
    const float* Wf   = (const float*)d_in[3];
    const float* bfp  = (const float*)d_in[4];
    const float* Wi   = (const float*)d_in[5];
    const float* bip  = (const float*)d_in[6];
    const float* Wo   = (const float*)d_in[7];
    const float* bop  = (const float*)d_in[8];
    const float* Wout = (const float*)d_in[9];
    const float* bout = (const float*)d_in[10];
    const int*   Np   = (const int*)d_in[11];
    float* out = (float*)d_out;

    dim3 g1(G3 / 128, B_ * T_ / 128);
    gemm_gx<<<g1, 256>>>(x, Wf, Wi, Wo, bfp, bip, bop, Np);

    lstm_rec<<<128, 384>>>(h0, c0, Wf, Wi, Wo, out, Np);

    dim3 g3(DOUT / 128, B_ * T_ / 128);
    gemm_out<<<g3, 256>>>(Wout, bout, out, Np);
}

// round 9
// speedup vs baseline: 1.4690x; 1.4690x over previous
#include <cuda_runtime.h>
#include <cstdint>

#define B_    64
#define T_    2048
#define DIN   256
#define DH    256
#define DC    256
#define DOUT  256
#define G3    768   // 3 gates * 256

// Scratch (allocation-free rule: __device__ globals)
__device__ float g_Gx[(size_t)B_ * T_ * G3];  // x-part gate preactivations (+bias)
__device__ float g_H [(size_t)B_ * T_ * DH];  // h_t for all t (for output GEMM)

// ---------------- helpers ----------------

__device__ __forceinline__ float2 ffma2(float2 a, float2 b, float2 c) {
    union U { float2 f; unsigned long long u; };
    U ua, ub, uc, ud;
    ua.f = a; ub.f = b; uc.f = c;
    asm("fma.rn.f32x2 %0, %1, %2, %3;"
        : "=l"(ud.u) : "l"(ua.u), "l"(ub.u), "l"(uc.u));
    return ud.f;
}

__device__ __forceinline__ uint32_t smem_u32(const void* p) {
    uint32_t a;
    asm("{ .reg .u64 t; cvta.to.shared.u64 t, %1; cvt.u32.u64 %0, t; }"
        : "=r"(a) : "l"(p));
    return a;
}

__device__ __forceinline__ void cluster_sync_() {
    asm volatile("barrier.cluster.arrive.aligned;" ::: "memory");
    asm volatile("barrier.cluster.wait.aligned;" ::: "memory");
}

__device__ __forceinline__ void mbar_init1(uint32_t mbar) {
    asm volatile("mbarrier.init.shared.b64 [%0], %1;" :: "r"(mbar), "r"(1u) : "memory");
}

__device__ __forceinline__ void mbar_expect(uint32_t mbar, uint32_t bytes) {
    asm volatile("mbarrier.arrive.expect_tx.shared.b64 _, [%0], %1;"
                 :: "r"(mbar), "r"(bytes) : "memory");
}

__device__ __forceinline__ void mbar_wait(uint32_t mbar, uint32_t parity) {
    asm volatile(
        "{\n\t"
        ".reg .pred P;\n"
        "W%=:\n\t"
        "mbarrier.try_wait.parity.acquire.cta.shared::cta.b64 P, [%0], %1, 0x989680;\n\t"
        "@P bra.uni D%=;\n\t"
        "bra.uni W%=;\n"
        "D%=:\n\t"
        "}"
        :: "r"(mbar), "r"(parity) : "memory");
}

// store one f32 into rank's smem + count 4 tx bytes on that rank's mbarrier
__device__ __forceinline__ void st_async_remote(uint32_t laddr, uint32_t lmbar,
                                                uint32_t rank, float v) {
    asm volatile(
        "{\n\t"
        ".reg .b32 ra, rb;\n\t"
        "mapa.shared::cluster.u32 ra, %0, %2;\n\t"
        "mapa.shared::cluster.u32 rb, %1, %2;\n\t"
        "st.async.shared::cluster.mbarrier::complete_tx::bytes.b32 [ra], %3, [rb];\n\t"
        "}"
        :: "r"(laddr), "r"(lmbar), "r"(rank), "r"(__float_as_uint(v)) : "memory");
}

__device__ __forceinline__ float sigmoidf_(float x) {
    return __fdividef(1.0f, 1.0f + __expf(-x));
}

__device__ __forceinline__ float tanhf_(float x) {
    return 1.0f - __fdividef(2.0f, 1.0f + __expf(2.0f * x));
}

// ================= GEMM core: 128x128 tile, BK=16, double-buffered =================

__global__ __launch_bounds__(256) void gemm_gx(
    const float* __restrict__ X,
    const float* __restrict__ Wf, const float* __restrict__ Wi, const float* __restrict__ Wo,
    const float* __restrict__ bf, const float* __restrict__ bi, const float* __restrict__ bo,
    const int* __restrict__ Np)
{
    const int N = *Np;
    const int m0 = blockIdx.y * 128;
    if (m0 >= B_ * N) return;
    const int j0v = blockIdx.x * 128;
    const int g  = j0v >> 8;
    const int d0 = j0v & 255;
    const float* Wg = (g == 0) ? Wf : ((g == 1) ? Wi : Wo);
    const float* bg = (g == 0) ? bf : ((g == 1) ? bi : bo);

    __shared__ float2 As2[2][8][128];
    __shared__ float2 Bs2[2][8][128];

    const int tid = threadIdx.x;
    const int tx = tid & 15, ty = tid >> 4;

    const int ra = tid >> 1, ha = tid & 1;
    int mg = m0 + ra; if (mg >= B_ * N) mg = B_ * N - 1;
    const int bb = mg / N, tt = mg % N;
    const float* arow = X + (size_t)(bb * T_ + tt) * DIN + 8 * ha;

    const int kp0 = tid >> 5;
    const int np0 = tid & 31;
    const float* bcol = Wg + d0 + 2 * np0;

    float4 a0, a1;
    float2 v00, v01, v10, v11;

    a0 = *reinterpret_cast<const float4*>(arow);
    a1 = *reinterpret_cast<const float4*>(arow + 4);
    v00 = *reinterpret_cast<const float2*>(bcol + (size_t)(2 * kp0) * DC);
    v01 = *reinterpret_cast<const float2*>(bcol + (size_t)(2 * kp0 + 1) * DC);
    v10 = *reinterpret_cast<const float2*>(bcol + (size_t)(2 * kp0) * DC + 64);
    v11 = *reinterpret_cast<const float2*>(bcol + (size_t)(2 * kp0 + 1) * DC + 64);

    As2[0][4 * ha + 0][ra] = make_float2(a0.x, a0.y);
    As2[0][4 * ha + 1][ra] = make_float2(a0.z, a0.w);
    As2[0][4 * ha + 2][ra] = make_float2(a1.x, a1.y);
    As2[0][4 * ha + 3][ra] = make_float2(a1.z, a1.w);
    *reinterpret_cast<float4*>(&Bs2[0][kp0][2 * np0]) =
        make_float4(v00.x, v01.x, v00.y, v01.y);
    *reinterpret_cast<float4*>(&Bs2[0][kp0][2 * np0 + 64]) =
        make_float4(v10.x, v11.x, v10.y, v11.y);
    __syncthreads();

    float2 acc[8][8];
    #pragma unroll
    for (int i = 0; i < 8; i++)
        #pragma unroll
        for (int j = 0; j < 8; j++) acc[i][j] = make_float2(0.f, 0.f);

    #pragma unroll 1
    for (int c = 0; c < 16; ++c) {
        const int buf = c & 1;
        if (c + 1 < 16) {
            const int kk = (c + 1) * 16;
            a0 = *reinterpret_cast<const float4*>(arow + kk);
            a1 = *reinterpret_cast<const float4*>(arow + kk + 4);
            v00 = *reinterpret_cast<const float2*>(bcol + (size_t)(kk + 2 * kp0) * DC);
            v01 = *reinterpret_cast<const float2*>(bcol + (size_t)(kk + 2 * kp0 + 1) * DC);
            v10 = *reinterpret_cast<const float2*>(bcol + (size_t)(kk + 2 * kp0) * DC + 64);
            v11 = *reinterpret_cast<const float2*>(bcol + (size_t)(kk + 2 * kp0 + 1) * DC + 64);
        }
        #pragma unroll
        for (int kp = 0; kp < 8; kp++) {
            float2 a2[8], b2[8];
            #pragma unroll
            for (int i = 0; i < 4; i++) {
                float4 t = *reinterpret_cast<const float4*>(&As2[buf][kp][32 * i + 2 * ty]);
                a2[2 * i]     = make_float2(t.x, t.y);
                a2[2 * i + 1] = make_float2(t.z, t.w);
            }
            #pragma unroll
            for (int j = 0; j < 4; j++) {
                float4 t = *reinterpret_cast<const float4*>(&Bs2[buf][kp][32 * j + 2 * tx]);
                b2[2 * j]     = make_float2(t.x, t.y);
                b2[2 * j + 1] = make_float2(t.z, t.w);
            }
            #pragma unroll
            for (int i = 0; i < 8; i++)
                #pragma unroll
                for (int j = 0; j < 8; j++)
                    acc[i][j] = ffma2(a2[i], b2[j], acc[i][j]);
        }
        if (c + 1 < 16) {
            const int nb = buf ^ 1;
            As2[nb][4 * ha + 0][ra] = make_float2(a0.x, a0.y);
            As2[nb][4 * ha + 1][ra] = make_float2(a0.z, a0.w);
            As2[nb][4 * ha + 2][ra] = make_float2(a1.x, a1.y);
            As2[nb][4 * ha + 3][ra] = make_float2(a1.z, a1.w);
            *reinterpret_cast<float4*>(&Bs2[nb][kp0][2 * np0]) =
                make_float4(v00.x, v01.x, v00.y, v01.y);
            *reinterpret_cast<float4*>(&Bs2[nb][kp0][2 * np0 + 64]) =
                make_float4(v10.x, v11.x, v10.y, v11.y);
        }
        __syncthreads();
    }

    float bgv[8];
    #pragma unroll
    for (int u = 0; u < 4; u++) {
        bgv[2 * u]     = bg[d0 + 32 * u + 2 * tx];
        bgv[2 * u + 1] = bg[d0 + 32 * u + 2 * tx + 1];
    }
    #pragma unroll
    for (int i = 0; i < 8; i++) {
        const int m = m0 + 32 * (i >> 1) + 2 * ty + (i & 1);
        if (m < B_ * N) {
            float* crow = g_Gx + (size_t)m * G3 + j0v;
            #pragma unroll
            for (int u = 0; u < 4; u++)
                *reinterpret_cast<float2*>(crow + 32 * u + 2 * tx) =
                    make_float2(acc[i][2 * u].x + acc[i][2 * u].y + bgv[2 * u],
                                acc[i][2 * u + 1].x + acc[i][2 * u + 1].y + bgv[2 * u + 1]);
        }
    }
}

// ---------------- GEMM 3: outs = sigmoid(H @ Wout + bout) ----------------

__global__ __launch_bounds__(256) void gemm_out(
    const float* __restrict__ Wout, const float* __restrict__ bout,
    float* __restrict__ out, const int* __restrict__ Np)
{
    const int N = *Np;
    const int m0 = blockIdx.y * 128;
    if (m0 >= B_ * N) return;
    const int j0v = blockIdx.x * 128;

    __shared__ float2 As2[2][8][128];
    __shared__ float2 Bs2[2][8][128];

    const int tid = threadIdx.x;
    const int tx = tid & 15, ty = tid >> 4;

    const int ra = tid >> 1, ha = tid & 1;
    int mg = m0 + ra; if (mg >= B_ * N) mg = B_ * N - 1;
    const float* arow = g_H + (size_t)mg * DH + 8 * ha;

    const int kp0 = tid >> 5;
    const int np0 = tid & 31;
    const float* bcol = Wout + j0v + 2 * np0;

    float4 a0, a1;
    float2 v00, v01, v10, v11;

    a0 = *reinterpret_cast<const float4*>(arow);
    a1 = *reinterpret_cast<const float4*>(arow + 4);
    v00 = *reinterpret_cast<const float2*>(bcol + (size_t)(2 * kp0) * DOUT);
    v01 = *reinterpret_cast<const float2*>(bcol + (size_t)(2 * kp0 + 1) * DOUT);
    v10 = *reinterpret_cast<const float2*>(bcol + (size_t)(2 * kp0) * DOUT + 64);
    v11 = *reinterpret_cast<const float2*>(bcol + (size_t)(2 * kp0 + 1) * DOUT + 64);

    As2[0][4 * ha + 0][ra] = make_float2(a0.x, a0.y);
    As2[0][4 * ha + 1][ra] = make_float2(a0.z, a0.w);
    As2[0][4 * ha + 2][ra] = make_float2(a1.x, a1.y);
    As2[0][4 * ha + 3][ra] = make_float2(a1.z, a1.w);
    *reinterpret_cast<float4*>(&Bs2[0][kp0][2 * np0]) =
        make_float4(v00.x, v01.x, v00.y, v01.y);
    *reinterpret_cast<float4*>(&Bs2[0][kp0][2 * np0 + 64]) =
        make_float4(v10.x, v11.x, v10.y, v11.y);
    __syncthreads();

    float2 acc[8][8];
    #pragma unroll
    for (int i = 0; i < 8; i++)
        #pragma unroll
        for (int j = 0; j < 8; j++) acc[i][j] = make_float2(0.f, 0.f);

    #pragma unroll 1
    for (int c = 0; c < 16; ++c) {
        const int buf = c & 1;
        if (c + 1 < 16) {
            const int kk = (c + 1) * 16;
            a0 = *reinterpret_cast<const float4*>(arow + kk);
            a1 = *reinterpret_cast<const float4*>(arow + kk + 4);
            v00 = *reinterpret_cast<const float2*>(bcol + (size_t)(kk + 2 * kp0) * DOUT);
            v01 = *reinterpret_cast<const float2*>(bcol + (size_t)(kk + 2 * kp0 + 1) * DOUT);
            v10 = *reinterpret_cast<const float2*>(bcol + (size_t)(kk + 2 * kp0) * DOUT + 64);
            v11 = *reinterpret_cast<const float2*>(bcol + (size_t)(kk + 2 * kp0 + 1) * DOUT + 64);
        }
        #pragma unroll
        for (int kp = 0; kp < 8; kp++) {
            float2 a2[8], b2[8];
            #pragma unroll
            for (int i = 0; i < 4; i++) {
                float4 t = *reinterpret_cast<const float4*>(&As2[buf][kp][32 * i + 2 * ty]);
                a2[2 * i]     = make_float2(t.x, t.y);
                a2[2 * i + 1] = make_float2(t.z, t.w);
            }
            #pragma unroll
            for (int j = 0; j < 4; j++) {
                float4 t = *reinterpret_cast<const float4*>(&Bs2[buf][kp][32 * j + 2 * tx]);
                b2[2 * j]     = make_float2(t.x, t.y);
                b2[2 * j + 1] = make_float2(t.z, t.w);
            }
            #pragma unroll
            for (int i = 0; i < 8; i++)
                #pragma unroll
                for (int j = 0; j < 8; j++)
                    acc[i][j] = ffma2(a2[i], b2[j], acc[i][j]);
        }
        if (c + 1 < 16) {
            const int nb = buf ^ 1;
            As2[nb][4 * ha + 0][ra] = make_float2(a0.x, a0.y);
            As2[nb][4 * ha + 1][ra] = make_float2(a0.z, a0.w);
            As2[nb][4 * ha + 2][ra] = make_float2(a1.x, a1.y);
            As2[nb][4 * ha + 3][ra] = make_float2(a1.z, a1.w);
            *reinterpret_cast<float4*>(&Bs2[nb][kp0][2 * np0]) =
                make_float4(v00.x, v01.x, v00.y, v01.y);
            *reinterpret_cast<float4*>(&Bs2[nb][kp0][2 * np0 + 64]) =
                make_float4(v10.x, v11.x, v10.y, v11.y);
        }
        __syncthreads();
    }

    float bgv[8];
    #pragma unroll
    for (int u = 0; u < 4; u++) {
        bgv[2 * u]     = bout[j0v + 32 * u + 2 * tx];
        bgv[2 * u + 1] = bout[j0v + 32 * u + 2 * tx + 1];
    }
    #pragma unroll
    for (int i = 0; i < 8; i++) {
        const int m = m0 + 32 * (i >> 1) + 2 * ty + (i & 1);
        if (m < B_ * N) {
            float* crow = out + (size_t)m * DOUT + j0v;
            #pragma unroll
            for (int u = 0; u < 4; u++)
                *reinterpret_cast<float2*>(crow + 32 * u + 2 * tx) =
                    make_float2(
                        sigmoidf_(acc[i][2 * u].x + acc[i][2 * u].y + bgv[2 * u]),
                        sigmoidf_(acc[i][2 * u + 1].x + acc[i][2 * u + 1].y + bgv[2 * u + 1]));
        }
    }
}

// ---------------- Recurrence: persistent, batch-parallel, 4-CTA clusters ----------------
// 32 clusters x 4 CTAs, batches {2c, 2c+1}. Rank r owns cell dims [r*64, r*64+64) for
// all 3 gates. GEMV thread mapping: lane quad-slot kq = lane&3 handles the interleaved
// k-subset {k : (k/4) mod 4 == kq}; each thread covers TWO adjacent gate-columns for
// both batches (128 FFMA2/thread). Per LDS.128 a warp touches 4 consecutive 16B lines
// (8-lane broadcast each) -> 1 phase; GEMV smem cost drops 4x vs the k-half scheme.
// Cross-kq reduction: 3-shuffle butterfly; every lane writes one pre-activation.
// h transport: direct st.async x4 (R7 proven), tx-counted mbarriers, double-buffered.

__global__ __launch_bounds__(384, 1) __cluster_dims__(4, 1, 1)
void lstm_rec(
    const float* __restrict__ h0, const float* __restrict__ c0,
    const float* __restrict__ Wf, const float* __restrict__ Wi, const float* __restrict__ Wo,
    float* __restrict__ out, const int* __restrict__ Np)
{
    const int N   = *Np;
    const int r   = blockIdx.x & 3;
    const int cid = blockIdx.x >> 2;
    const int b0  = cid * 2;
    const int tid = threadIdx.x;

    __shared__ __align__(16) float h_s[2][2][256];   // [parity][batch][dim]
    __shared__ float pre_s[2][208];                  // [batch][col] (pad 208: bank-disjoint)
    __shared__ __align__(8) unsigned long long mbar[2];

    const int lane = tid & 31;
    const int wrp  = tid >> 5;
    const int kq   = lane & 3;                        // k-interleave slot
    const int cc0  = wrp * 16 + ((lane >> 2) << 1);   // first of 2 local gate-cols
    const int g0   = cc0 >> 6;                        // gate (same for both cols)
    const int gd0  = r * 64 + (cc0 & 63);             // weight-matrix column of cc0
    const float* Wg = (g0 == 0) ? Wf : ((g0 == 1) ? Wi : Wo);

    // weights: w0/w1 = cols cc0/cc0+1; per line li: k0 = 4*kq + 16*li (h-part rows +256)
    float2 w0[32], w1[32];
    #pragma unroll
    for (int li = 0; li < 16; li++) {
        const int k0 = 4 * kq + 16 * li;
        const float* p0 = Wg + (size_t)(256 + k0) * DC + gd0;
        w0[2 * li]     = make_float2(p0[0],          p0[DC]);
        w0[2 * li + 1] = make_float2(p0[2 * DC],     p0[3 * DC]);
        w1[2 * li]     = make_float2(p0[1],          p0[DC + 1]);
        w1[2 * li + 1] = make_float2(p0[2 * DC + 1], p0[3 * DC + 1]);
    }

    // writer identity after reduction: lane kq ends with target (bw, cw)
    const int bw = kq >> 1;
    const int cw = cc0 + (kq & 1);
    const int gcolw = (cw >> 6) * 256 + r * 64 + (cw & 63);   // col in Gx layout [f|i|o]

    const uint32_t mb0 = smem_u32(&mbar[0]);
    const uint32_t mb1 = smem_u32(&mbar[1]);
    if (tid == 0) {
        mbar_init1(mb0);
        mbar_init1(mb1);
        mbar_expect(mb0, 2048);   // first use: h for step 2
        mbar_expect(mb1, 2048);   // first use: h for step 1
    }

    // init h (parity 0)
    for (int i = tid; i < 512; i += 384) {
        const int b = i >> 8, d = i & 255;
        h_s[0][b][d] = h0[(b0 + b) * DH + d];
    }
    float c_st = 0.f, h_loc = 0.f;
    const int pb = (tid < 128) ? (tid >> 6) : 0;
    const int pd = (tid < 128) ? (tid & 63) : 0;
    if (tid < 128) c_st = c0[(b0 + pb) * DC + r * 64 + pd];
    __syncthreads();
    cluster_sync_();   // all mbarriers initialized before any DSMEM traffic

    float gx = g_Gx[((size_t)(b0 + bw) * N + 0) * G3 + gcolw];

    float* out_hf = out + (size_t)B_ * N * DOUT;
    float* out_cf = out_hf + B_ * DH;

    int ph0 = 0, ph1 = 0;

    for (int t = 0; t < N; t++) {
        const int p = t & 1;

        if (t > 0) {
            const uint32_t mb = p ? mb1 : mb0;
            mbar_wait(mb, (uint32_t)(p ? ph1 : ph0));
            if (p) ph1 ^= 1; else ph0 ^= 1;
            if (tid == 0) mbar_expect(mb, 2048);   // re-arm for step t+2
        }

        const float gxc = gx;
        const int tn = (t + 1 < N) ? (t + 1) : t;
        gx = g_Gx[((size_t)(b0 + bw) * N + tn) * G3 + gcolw];

        // GEMV: acc[col][batch], h lines at byte offset kq*16 + li*64
        float2 a00 = make_float2(0.f, 0.f), a10 = a00, a01 = a00, a11 = a00;
        {
            const float4* hp0 = reinterpret_cast<const float4*>(&h_s[p][0][4 * kq]);
            const float4* hp1 = reinterpret_cast<const float4*>(&h_s[p][1][4 * kq]);
            #pragma unroll
            for (int li = 0; li < 16; li++) {
                float4 hv = hp0[4 * li];
                float2 hlo = make_float2(hv.x, hv.y), hhi = make_float2(hv.z, hv.w);
                a00 = ffma2(hlo, w0[2 * li], a00);
                a00 = ffma2(hhi, w0[2 * li + 1], a00);
                a10 = ffma2(hlo, w1[2 * li], a10);
                a10 = ffma2(hhi, w1[2 * li + 1], a10);
            }
            #pragma unroll
            for (int li = 0; li < 16; li++) {
                float4 hv = hp1[4 * li];
                float2 hlo = make_float2(hv.x, hv.y), hhi = make_float2(hv.z, hv.w);
                a01 = ffma2(hlo, w0[2 * li], a01);
                a01 = ffma2(hhi, w0[2 * li + 1], a01);
                a11 = ffma2(hlo, w1[2 * li], a11);
                a11 = ffma2(hhi, w1[2 * li + 1], a11);
            }
        }
        // targets: 0=(b0,c0) 1=(b0,c1) 2=(b1,c0) 3=(b1,c1)
        const float v0 = a00.x + a00.y;
        const float v1 = a10.x + a10.y;
        const float v2 = a01.x + a01.y;
        const float v3 = a11.x + a11.y;

        const bool bit0 = (kq & 1), bit1 = (kq & 2);
        // round 1 (xor 1): combine kq-pairs; packed send/keep
        float sendA = bit0 ? v0 : v1, keepA = bit0 ? v1 : v0;
        float tA = keepA + __shfl_xor_sync(0xffffffffu, sendA, 1);
        float sendB = bit0 ? v2 : v3, keepB = bit0 ? v3 : v2;
        float tB = keepB + __shfl_xor_sync(0xffffffffu, sendB, 1);
        // round 2 (xor 2): combine kq-half-pairs
        float send2 = bit1 ? tA : tB, keep2 = bit1 ? tB : tA;
        float sfin = keep2 + __shfl_xor_sync(0xffffffffu, send2, 2);

        pre_s[bw][cw] = sfin + gxc;
        __syncthreads();

        if (tid < 128) {
            const float pf = pre_s[pb][pd];
            const float pi = pre_s[pb][64 + pd];
            const float po = pre_s[pb][128 + pd];
            const float f  = sigmoidf_(pf);
            const float ig = sigmoidf_(pi);
            const float z  = tanhf_(pi);
            const float o  = sigmoidf_(po);
            c_st  = c_st * f + z * ig;
            h_loc = tanhf_(c_st) * o;

            if (t + 1 < N) {
                // push h chunk to all 4 ranks' h_s[1-p] + count tx on their mbar
                const uint32_t la = smem_u32(&h_s[1 - p][pb][r * 64 + pd]);
                const uint32_t lb = p ? mb0 : mb1;
                st_async_remote(la, lb, 0u, h_loc);
                st_async_remote(la, lb, 1u, h_loc);
                st_async_remote(la, lb, 2u, h_loc);
                st_async_remote(la, lb, 3u, h_loc);
            }
            g_H[((size_t)(b0 + pb) * N + t) * DH + r * 64 + pd] = h_loc;
        }
    }

    if (tid < 128) {
        out_hf[(b0 + pb) * DH + r * 64 + pd] = h_loc;
        out_cf[(b0 + pb) * DC + r * 64 + pd] = c_st;
    }
    cluster_sync_();   // no CTA exits while peers could still be mid-step
}

// ---------------- launch ----------------

extern "C" void kernel_launch(void* const* d_in, const int* in_sizes, int n_in,
                              void* d_out, int out_size) {
    const float* x    = (const float*)d_in[0];
    const float* h0   = (const float*)d_in[1];
    const float* c0   = (const float*)d_in[2];
    const float* Wf   = (const float*)d_in[3];
    const float* bfp  = (const float*)d_in[4];
    const float* Wi   = (const float*)d_in[5];
    const float* bip  = (const float*)d_in[6];
    const float* Wo   = (const float*)d_in[7];
    const float* bop  = (const float*)d_in[8];
    const float* Wout = (const float*)d_in[9];
    const float* bout = (const float*)d_in[10];
    const int*   Np   = (const int*)d_in[11];
    float* out = (float*)d_out;

    dim3 g1(G3 / 128, B_ * T_ / 128);
    gemm_gx<<<g1, 256>>>(x, Wf, Wi, Wo, bfp, bip, bop, Np);

    lstm_rec<<<128, 384>>>(h0, c0, Wf, Wi, Wo, out, Np);

    dim3 g3(DOUT / 128, B_ * T_ / 128);
    gemm_out<<<g3, 256>>>(Wout, bout, out, Np);
}